// round 5
// baseline (speedup 1.0000x reference)
#include <cuda_runtime.h>
#include <cuda_bf16.h>

#define NN   50000
#define EE   800000
#define IN_F 256
#define HID_F 256
#define OUT_F 128

// ---------------- static device scratch (no allocation allowed) ----------------
__device__ int   g_cnt[NN];
__device__ int   g_rowptr[NN + 1];
__device__ int   g_cursor[NN];
__device__ int   g_srt_src[EE];
__device__ float g_srt_w[EE];
__device__ float g_B1[NN * 256];   // spmm1 result; later reused as MLP hidden
__device__ float g_B2[NN * 256];   // h1
__device__ float g_B3[NN * 128];   // h1 @ W2 (pre-spmm2)

// ---------------- CSR build ----------------
__global__ void k_clear_cnt() {
    int i = blockIdx.x * blockDim.x + threadIdx.x;
    if (i < NN) g_cnt[i] = 0;
}

__global__ void k_hist(const int* __restrict__ dst) {
    int e = blockIdx.x * blockDim.x + threadIdx.x;
    if (e < EE) atomicAdd(&g_cnt[dst[e]], 1);
}

// single-block exclusive scan over 50000 counts -> rowptr, cursor
__global__ void k_scan() {
    __shared__ int warp_sums[32];
    int t = threadIdx.x;
    int lane = t & 31, wid = t >> 5;
    int carry = 0;
    for (int base = 0; base < NN; base += 1024) {
        int i = base + t;
        int v = (i < NN) ? g_cnt[i] : 0;
        int x = v;
        #pragma unroll
        for (int o = 1; o < 32; o <<= 1) {
            int y = __shfl_up_sync(0xFFFFFFFFu, x, o);
            if (lane >= o) x += y;
        }
        if (lane == 31) warp_sums[wid] = x;
        __syncthreads();
        if (wid == 0) {
            int s = warp_sums[lane];
            #pragma unroll
            for (int o = 1; o < 32; o <<= 1) {
                int y = __shfl_up_sync(0xFFFFFFFFu, s, o);
                if (lane >= o) s += y;
            }
            warp_sums[lane] = s;
        }
        __syncthreads();
        int warp_off = (wid == 0) ? 0 : warp_sums[wid - 1];
        int excl = carry + warp_off + x - v;
        if (i < NN) { g_rowptr[i] = excl; g_cursor[i] = excl; }
        int tot = warp_sums[31];
        __syncthreads();
        carry += tot;
    }
    if (t == 0) g_rowptr[NN] = carry;
}

__global__ void k_scatter(const int* __restrict__ src, const int* __restrict__ dst,
                          const float* __restrict__ w) {
    int e = blockIdx.x * blockDim.x + threadIdx.x;
    if (e < EE) {
        int p = atomicAdd(&g_cursor[dst[e]], 1);
        g_srt_src[p] = src[e];
        g_srt_w[p]   = w[e];
    }
}

// ---------------- gather SpMM (warp per destination node) ----------------
__global__ __launch_bounds__(256) void k_spmm256(const float* __restrict__ x,
                                                 float* __restrict__ y) {
    int gw = (blockIdx.x * blockDim.x + threadIdx.x) >> 5;
    if (gw >= NN) return;
    int lane = threadIdx.x & 31;
    float4 a0 = make_float4(0.f, 0.f, 0.f, 0.f);
    float4 a1 = a0;
    int s = g_rowptr[gw], e = g_rowptr[gw + 1];
    for (int i = s; i < e; i++) {
        int   src = g_srt_src[i];
        float w   = g_srt_w[i];
        const float4* p = (const float4*)(x + (size_t)src * 256) + lane;
        float4 u = p[0];
        float4 v = p[32];
        a0.x += w * u.x; a0.y += w * u.y; a0.z += w * u.z; a0.w += w * u.w;
        a1.x += w * v.x; a1.y += w * v.y; a1.z += w * v.z; a1.w += w * v.w;
    }
    float4* o = (float4*)(y + (size_t)gw * 256) + lane;
    o[0]  = a0;
    o[32] = a1;
}

__global__ __launch_bounds__(256) void k_spmm128(const float* __restrict__ x,
                                                 float* __restrict__ y, int ldy) {
    int gw = (blockIdx.x * blockDim.x + threadIdx.x) >> 5;
    if (gw >= NN) return;
    int lane = threadIdx.x & 31;
    float4 a0 = make_float4(0.f, 0.f, 0.f, 0.f);
    int s = g_rowptr[gw], e = g_rowptr[gw + 1];
    for (int i = s; i < e; i++) {
        int   src = g_srt_src[i];
        float w   = g_srt_w[i];
        const float4* p = (const float4*)(x + (size_t)src * 128) + lane;
        float4 u = p[0];
        a0.x += w * u.x; a0.y += w * u.y; a0.z += w * u.z; a0.w += w * u.w;
    }
    float4* o = (float4*)(y + (size_t)gw * ldy) + lane;
    o[0] = a0;
}

// ---------------- fp32 SGEMM: C = op(A[MxK] @ B[KxN] + bias), optional relu,
// optional secondary destination (for h1 dual-store into the output) ----------------
#define BM 128
#define BN 128
#define BKD 16
#define TM 8
#define TN 8

__global__ __launch_bounds__(256, 2) void k_sgemm(
    const float* __restrict__ A, const float* __restrict__ B,
    const float* __restrict__ bias,
    float* __restrict__ C, int ldc,
    float* __restrict__ C2, int ldc2,
    int M, int Nc, int K, int do_relu)
{
    __shared__ float As[BKD][BM + 4];
    __shared__ float Bs[BKD][BN];

    int tid = threadIdx.x;
    int tx = tid & 15;   // N dir (16 * 8 = 128)
    int ty = tid >> 4;   // M dir (16 * 8 = 128)
    int bm = blockIdx.y * BM;
    int bn = blockIdx.x * BN;

    float acc[TM][TN];
    #pragma unroll
    for (int i = 0; i < TM; i++)
        #pragma unroll
        for (int j = 0; j < TN; j++) acc[i][j] = 0.f;

    int a_row = tid >> 2;          // 0..63
    int a_col = (tid & 3) * 4;     // 0,4,8,12
    int b_row = tid >> 5;          // 0..7
    int b_col = (tid & 31) * 4;    // 0..124

    for (int k0 = 0; k0 < K; k0 += BKD) {
        #pragma unroll
        for (int p = 0; p < 2; p++) {
            int r  = a_row + p * 64;
            int gm = bm + r;
            float4 v = make_float4(0.f, 0.f, 0.f, 0.f);
            if (gm < M) v = *(const float4*)(A + (size_t)gm * K + k0 + a_col);
            As[a_col + 0][r] = v.x;
            As[a_col + 1][r] = v.y;
            As[a_col + 2][r] = v.z;
            As[a_col + 3][r] = v.w;
        }
        #pragma unroll
        for (int p = 0; p < 2; p++) {
            int r = b_row + p * 8;
            *(float4*)&Bs[r][b_col] =
                *(const float4*)(B + (size_t)(k0 + r) * Nc + bn + b_col);
        }
        __syncthreads();

        #pragma unroll
        for (int k = 0; k < BKD; k++) {
            float4 ra0 = *(float4*)&As[k][ty * TM];
            float4 ra1 = *(float4*)&As[k][ty * TM + 4];
            float4 rb0 = *(float4*)&Bs[k][tx * TN];
            float4 rb1 = *(float4*)&Bs[k][tx * TN + 4];
            float ra[TM] = {ra0.x, ra0.y, ra0.z, ra0.w, ra1.x, ra1.y, ra1.z, ra1.w};
            float rb[TN] = {rb0.x, rb0.y, rb0.z, rb0.w, rb1.x, rb1.y, rb1.z, rb1.w};
            #pragma unroll
            for (int i = 0; i < TM; i++)
                #pragma unroll
                for (int j = 0; j < TN; j++)
                    acc[i][j] += ra[i] * rb[j];
        }
        __syncthreads();
    }

    #pragma unroll
    for (int i = 0; i < TM; i++) {
        int gm = bm + ty * TM + i;
        if (gm >= M) continue;
        #pragma unroll
        for (int j = 0; j < TN; j += 4) {
            int gn = bn + tx * TN + j;
            float4 v = make_float4(acc[i][j], acc[i][j + 1], acc[i][j + 2], acc[i][j + 3]);
            if (bias) {
                v.x += bias[gn];     v.y += bias[gn + 1];
                v.z += bias[gn + 2]; v.w += bias[gn + 3];
            }
            if (do_relu) {
                v.x = fmaxf(v.x, 0.f); v.y = fmaxf(v.y, 0.f);
                v.z = fmaxf(v.z, 0.f); v.w = fmaxf(v.w, 0.f);
            }
            *(float4*)(C + (size_t)gm * ldc + gn) = v;
            if (C2) *(float4*)(C2 + (size_t)gm * ldc2 + gn) = v;
        }
    }
}

// ---------------- launch ----------------
extern "C" void kernel_launch(void* const* d_in, const int* in_sizes, int n_in,
                              void* d_out, int out_size) {
    const float* features = (const float*)d_in[0];
    const int*   edge_src = (const int*)d_in[1];
    const int*   edge_dst = (const int*)d_in[2];
    const float* edge_w   = (const float*)d_in[3];
    const float* W1       = (const float*)d_in[4];
    const float* W2       = (const float*)d_in[5];
    const float* mlp_w1   = (const float*)d_in[6];
    const float* mlp_b1   = (const float*)d_in[7];
    const float* mlp_w2   = (const float*)d_in[8];
    const float* mlp_b2   = (const float*)d_in[9];
    float* out = (float*)d_out;

    void *pv;
    cudaGetSymbolAddress(&pv, g_B1); float* B1 = (float*)pv;
    cudaGetSymbolAddress(&pv, g_B2); float* B2 = (float*)pv;
    cudaGetSymbolAddress(&pv, g_B3); float* B3 = (float*)pv;

    const int E_BLKS = (EE + 255) / 256;
    const int N_BLKS = (NN + 255) / 256;
    const int SPMM_BLKS = (NN * 32 + 255) / 256;   // warp per node

    // CSR build by destination
    k_clear_cnt<<<N_BLKS, 256>>>();
    k_hist<<<E_BLKS, 256>>>(edge_dst);
    k_scan<<<1, 1024>>>();
    k_scatter<<<E_BLKS, 256>>>(edge_src, edge_dst, edge_w);

    // t1 = A @ X    [N,256]
    k_spmm256<<<SPMM_BLKS, 256>>>(features, B1);

    // h1 = relu(t1 @ W1)  -> B2 and out[:,128:384]
    {
        dim3 grid(HID_F / BN, (NN + BM - 1) / BM);
        k_sgemm<<<grid, 256>>>(B1, W1, nullptr, B2, 256, out + 128, 512,
                               NN, HID_F, 256, 1);
    }
    // g = h1 @ W2   [N,128]  (reassociation: A@(h1@W2) instead of (A@h1)@W2)
    {
        dim3 grid(OUT_F / BN, (NN + BM - 1) / BM);
        k_sgemm<<<grid, 256>>>(B2, W2, nullptr, B3, 128, nullptr, 0,
                               NN, OUT_F, 256, 0);
    }
    // h2 = A @ g -> out[:,384:512]
    k_spmm128<<<SPMM_BLKS, 256>>>(B3, out + 384, 512);

    // MLP hidden = relu(X @ mlp_w1 + b1) -> B1 (reuse)
    {
        dim3 grid(HID_F / BN, (NN + BM - 1) / BM);
        k_sgemm<<<grid, 256>>>(features, mlp_w1, mlp_b1, B1, 256, nullptr, 0,
                               NN, HID_F, 256, 1);
    }
    // self_out = hidden @ mlp_w2 + b2 -> out[:,0:128]
    {
        dim3 grid(OUT_F / BN, (NN + BM - 1) / BM);
        k_sgemm<<<grid, 256>>>(B1, mlp_w2, mlp_b2, out, 512, nullptr, 0,
                               NN, OUT_F, 256, 0);
    }
    (void)in_sizes; (void)n_in; (void)out_size;
}

// round 7
// speedup vs baseline: 1.7597x; 1.7597x over previous
#include <cuda_runtime.h>
#include <cuda_fp16.h>
#include <cstdint>

#define NN   50000
#define EE   800000
#define IN_F 256
#define HID_F 256
#define OUT_F 128

// ---------------- static device scratch (no allocation allowed) ----------------
__device__ int   g_cnt[NN];
__device__ int   g_rowptr[NN + 1];
__device__ int   g_cursor[NN];
__device__ int   g_srt_src[EE];
__device__ float g_srt_w[EE];
__device__ float g_B3[NN * 128];          // h1 @ W2 (pre-spmm2), fp32

// fp16 split activation buffers
__device__ __half g_Ah1[NN * 256];
__device__ __half g_Al1[NN * 256];
__device__ __half g_Ah2[NN * 256];
__device__ __half g_Al2[NN * 256];

// fp16 split transposed weights  B[n][k] = W[k][n]
__device__ __half g_W1h[256 * 256], g_W1l[256 * 256];
__device__ __half g_W2h[128 * 256], g_W2l[128 * 256];
__device__ __half g_M1h[256 * 256], g_M1l[256 * 256];
__device__ __half g_M2h[128 * 256], g_M2l[128 * 256];

// ---------------- PTX helpers (sm_80-era only: cp.async, ldmatrix, mma.sync) ----
__device__ __forceinline__ uint32_t smem_u32(const void* p) {
    uint32_t a;
    asm("{ .reg .u64 t; cvta.to.shared.u64 t, %1; cvt.u32.u64 %0, t; }" : "=r"(a) : "l"(p));
    return a;
}
__device__ __forceinline__ void cp16(uint32_t d, const void* s) {
    asm volatile("cp.async.cg.shared.global [%0], [%1], 16;" :: "r"(d), "l"(s) : "memory");
}
#define CP_COMMIT() asm volatile("cp.async.commit_group;" ::: "memory")
#define CP_WAIT(n)  asm volatile("cp.async.wait_group %0;" :: "n"(n) : "memory")

#define LDSM4(r0, r1, r2, r3, a) \
    asm volatile("ldmatrix.sync.aligned.m8n8.x4.shared.b16 {%0,%1,%2,%3}, [%4];" \
                 : "=r"(r0), "=r"(r1), "=r"(r2), "=r"(r3) : "r"(a))

#define MMA16816(c, a, b) \
    asm volatile("mma.sync.aligned.m16n8k16.row.col.f32.f16.f16.f32 " \
                 "{%0,%1,%2,%3}, {%4,%5,%6,%7}, {%8,%9}, {%0,%1,%2,%3};" \
                 : "+f"((c)[0]), "+f"((c)[1]), "+f"((c)[2]), "+f"((c)[3]) \
                 : "r"((a)[0]), "r"((a)[1]), "r"((a)[2]), "r"((a)[3]), \
                   "r"((b)[0]), "r"((b)[1]))

__device__ __forceinline__ uint32_t swz(uint32_t o) { return o ^ ((o >> 3) & 0x70); }

// ---------------- CSR build ----------------
__global__ void k_clear_cnt() {
    int i = blockIdx.x * blockDim.x + threadIdx.x;
    if (i < NN) g_cnt[i] = 0;
}

__global__ void k_hist(const int* __restrict__ dst) {
    int e = blockIdx.x * blockDim.x + threadIdx.x;
    if (e < EE) atomicAdd(&g_cnt[dst[e]], 1);
}

__global__ void k_scan() {
    __shared__ int warp_sums[32];
    int t = threadIdx.x;
    int lane = t & 31, wid = t >> 5;
    int carry = 0;
    for (int base = 0; base < NN; base += 1024) {
        int i = base + t;
        int v = (i < NN) ? g_cnt[i] : 0;
        int x = v;
        #pragma unroll
        for (int o = 1; o < 32; o <<= 1) {
            int y = __shfl_up_sync(0xFFFFFFFFu, x, o);
            if (lane >= o) x += y;
        }
        if (lane == 31) warp_sums[wid] = x;
        __syncthreads();
        if (wid == 0) {
            int s = warp_sums[lane];
            #pragma unroll
            for (int o = 1; o < 32; o <<= 1) {
                int y = __shfl_up_sync(0xFFFFFFFFu, s, o);
                if (lane >= o) s += y;
            }
            warp_sums[lane] = s;
        }
        __syncthreads();
        int warp_off = (wid == 0) ? 0 : warp_sums[wid - 1];
        int excl = carry + warp_off + x - v;
        if (i < NN) { g_rowptr[i] = excl; g_cursor[i] = excl; }
        int tot = warp_sums[31];
        __syncthreads();
        carry += tot;
    }
    if (t == 0) g_rowptr[NN] = carry;
}

__global__ void k_scatter(const int* __restrict__ src, const int* __restrict__ dst,
                          const float* __restrict__ w) {
    int e = blockIdx.x * blockDim.x + threadIdx.x;
    if (e < EE) {
        int p = atomicAdd(&g_cursor[dst[e]], 1);
        g_srt_src[p] = src[e];
        g_srt_w[p]   = w[e];
    }
}

// ---------------- fp32 -> (hi, lo) fp16 split helpers ----------------
__device__ __forceinline__ void split2(float p, float q, __half* yh, __half* yl) {
    __half h0 = __float2half_rn(p), h1 = __float2half_rn(q);
    __half l0 = __float2half_rn(p - __half2float(h0));
    __half l1 = __float2half_rn(q - __half2float(h1));
    *(__half2*)yh = __halves2half2(h0, h1);
    *(__half2*)yl = __halves2half2(l0, l1);
}

// ---------------- gather SpMM: out in split fp16 (warp per dst node) ----------------
__global__ __launch_bounds__(256) void k_spmm256(const float* __restrict__ x,
                                                 __half* __restrict__ yh,
                                                 __half* __restrict__ yl) {
    int gw = (blockIdx.x * blockDim.x + threadIdx.x) >> 5;
    if (gw >= NN) return;
    int lane = threadIdx.x & 31;
    float4 a0 = make_float4(0.f, 0.f, 0.f, 0.f);
    float4 a1 = a0;
    int s = g_rowptr[gw], e = g_rowptr[gw + 1];
    for (int i = s; i < e; i++) {
        int   src = g_srt_src[i];
        float w   = g_srt_w[i];
        const float4* p = (const float4*)(x + (size_t)src * 256) + lane;
        float4 u = p[0];
        float4 v = p[32];
        a0.x += w * u.x; a0.y += w * u.y; a0.z += w * u.z; a0.w += w * u.w;
        a1.x += w * v.x; a1.y += w * v.y; a1.z += w * v.z; a1.w += w * v.w;
    }
    size_t base = (size_t)gw * 256 + lane * 4;
    split2(a0.x, a0.y, yh + base,       yl + base);
    split2(a0.z, a0.w, yh + base + 2,   yl + base + 2);
    split2(a1.x, a1.y, yh + base + 128, yl + base + 128);
    split2(a1.z, a1.w, yh + base + 130, yl + base + 130);
}

__global__ __launch_bounds__(256) void k_spmm128(const float* __restrict__ x,
                                                 float* __restrict__ y, int ldy) {
    int gw = (blockIdx.x * blockDim.x + threadIdx.x) >> 5;
    if (gw >= NN) return;
    int lane = threadIdx.x & 31;
    float4 a0 = make_float4(0.f, 0.f, 0.f, 0.f);
    int s = g_rowptr[gw], e = g_rowptr[gw + 1];
    for (int i = s; i < e; i++) {
        int   src = g_srt_src[i];
        float w   = g_srt_w[i];
        const float4* p = (const float4*)(x + (size_t)src * 128) + lane;
        float4 u = p[0];
        a0.x += w * u.x; a0.y += w * u.y; a0.z += w * u.z; a0.w += w * u.w;
    }
    float4* o = (float4*)(y + (size_t)gw * ldy) + lane;
    o[0] = a0;
}

// ---------------- conversion kernels ----------------
__global__ void k_cvt_w(const float* __restrict__ W, __half* __restrict__ bh,
                        __half* __restrict__ bl, int Nn) {
    int i = blockIdx.x * blockDim.x + threadIdx.x;
    if (i >= Nn * 256) return;
    int n = i >> 8, k = i & 255;
    float x = W[k * Nn + n];
    __half h = __float2half_rn(x);
    bh[i] = h;
    bl[i] = __float2half_rn(x - __half2float(h));
}

__global__ void k_cvt_feat(const float4* __restrict__ f, __half* __restrict__ yh,
                           __half* __restrict__ yl) {
    int i = blockIdx.x * blockDim.x + threadIdx.x;
    if (i >= NN * 64) return;
    float4 v = f[i];
    size_t o = (size_t)i * 4;
    split2(v.x, v.y, yh + o,     yl + o);
    split2(v.z, v.w, yh + o + 2, yl + o + 2);
}

// ---------------- split-fp16 mma.sync GEMM ----------------
// D[128,128] tile = (Ah+Al)[M,256] @ (Bh+Bl)[Ntile,256]^T, fp32 accum,
// 3-product split (Ah·Bh + Ah·Bl + Al·Bh). K chunks of 64 halves, 2-stage cp.async.
// SMEM stage layout (SW128 swizzled, 128B rows of 64 halves):
//   +0      Ah tile 128x64
//   +16384  Al tile
//   +32768  Bh tile 128x64
//   +49152  Bl tile
#define STG_SZ 65536

__global__ __launch_bounds__(256, 1) void k_hgemm(
    const __half* __restrict__ Ah, const __half* __restrict__ Al,
    const __half* __restrict__ Bh, const __half* __restrict__ Bl,
    const float* __restrict__ bias,
    float* __restrict__ C, int ldc,
    __half* __restrict__ Ch, __half* __restrict__ Cl,
    int M, int relu)
{
    extern __shared__ char smem[];
    uint32_t sb = smem_u32(smem);

    int t    = threadIdx.x;
    int lane = t & 31;
    int wid  = t >> 5;
    int wm   = wid & 3;          // 4 warps along M (32 rows each)
    int wn   = wid >> 2;         // 2 warps along N (64 cols each)
    int bm   = blockIdx.y * 128;
    int bn   = blockIdx.x * 128;

    float acc[2][8][4];
    #pragma unroll
    for (int i = 0; i < 2; i++)
        #pragma unroll
        for (int j = 0; j < 8; j++)
            #pragma unroll
            for (int q = 0; q < 4; q++) acc[i][j][q] = 0.f;

    // -------- loaders: 4 buffers x 128 rows x 8 chunks(16B); 256 thr x 4 iters --------
    auto LOADC = [&](int c) {
        uint32_t st = sb + (c & 1) * STG_SZ;
        #pragma unroll
        for (int i = 0; i < 4; i++) {
            int id  = t + 256 * i;
            int row = id >> 3;
            int c16 = id & 7;
            uint32_t s = swz((uint32_t)row * 128 + c16 * 16);
            int ar = bm + row; if (ar >= M) ar = M - 1;
            size_t ga = (size_t)ar * 256 + c * 64 + c16 * 8;
            size_t gb = (size_t)(bn + row) * 256 + c * 64 + c16 * 8;
            cp16(st +         s, Ah + ga);
            cp16(st + 16384 + s, Al + ga);
            cp16(st + 32768 + s, Bh + gb);
            cp16(st + 49152 + s, Bl + gb);
        }
        CP_COMMIT();
    };

    auto COMPUTE = [&](int c) {
        uint32_t st  = sb + (c & 1) * STG_SZ;
        uint32_t bAh = st, bAl = st + 16384, bBh = st + 32768, bBl = st + 49152;
        #pragma unroll
        for (int ks = 0; ks < 4; ks++) {
            uint32_t ah[2][4], al[2][4], bh[8][2], bl[8][2];
            #pragma unroll
            for (int i = 0; i < 2; i++) {
                uint32_t o = swz(((uint32_t)(wm * 32 + i * 16 + (lane & 15)) << 7)
                                 + ks * 32 + ((lane >> 4) << 4));
                LDSM4(ah[i][0], ah[i][1], ah[i][2], ah[i][3], bAh + o);
                LDSM4(al[i][0], al[i][1], al[i][2], al[i][3], bAl + o);
            }
            #pragma unroll
            for (int j = 0; j < 8; j += 2) {
                uint32_t o = swz(((uint32_t)(wn * 64 + (j + (lane >> 4)) * 8 + (lane & 7)) << 7)
                                 + ks * 32 + (((lane >> 3) & 1) << 4));
                LDSM4(bh[j][0], bh[j][1], bh[j+1][0], bh[j+1][1], bBh + o);
                LDSM4(bl[j][0], bl[j][1], bl[j+1][0], bl[j+1][1], bBl + o);
            }
            #pragma unroll
            for (int i = 0; i < 2; i++)
                #pragma unroll
                for (int j = 0; j < 8; j++) {
                    MMA16816(acc[i][j], ah[i], bh[j]);
                    MMA16816(acc[i][j], ah[i], bl[j]);
                    MMA16816(acc[i][j], al[i], bh[j]);
                }
        }
    };

    LOADC(0);
    LOADC(1);

    #pragma unroll
    for (int c = 0; c < 4; c++) {
        if (c < 3) { CP_WAIT(1); } else { CP_WAIT(0); }
        __syncthreads();
        COMPUTE(c);
        __syncthreads();
        if (c + 2 < 4) LOADC(c + 2);
    }

    // -------- epilogue: c-frag layout m16n8 --------
    int gid = lane >> 2;               // 0..7
    int qid = lane & 3;                // 0..3
    #pragma unroll
    for (int i = 0; i < 2; i++) {
        #pragma unroll
        for (int j = 0; j < 8; j++) {
            int col = bn + wn * 64 + j * 8 + qid * 2;
            float b0 = 0.f, b1 = 0.f;
            if (bias) { b0 = bias[col]; b1 = bias[col + 1]; }
            #pragma unroll
            for (int h = 0; h < 2; h++) {
                int gm = bm + wm * 32 + i * 16 + gid + h * 8;
                if (gm >= M) continue;
                float v0 = acc[i][j][2*h + 0] + b0;
                float v1 = acc[i][j][2*h + 1] + b1;
                if (relu) { v0 = fmaxf(v0, 0.f); v1 = fmaxf(v1, 0.f); }
                if (C) *(float2*)(C + (size_t)gm * ldc + col) = make_float2(v0, v1);
                if (Ch) split2(v0, v1, Ch + (size_t)gm * 256 + col,
                                        Cl + (size_t)gm * 256 + col);
            }
        }
    }
}

// ---------------- launch ----------------
extern "C" void kernel_launch(void* const* d_in, const int* in_sizes, int n_in,
                              void* d_out, int out_size) {
    const float* features = (const float*)d_in[0];
    const int*   edge_src = (const int*)d_in[1];
    const int*   edge_dst = (const int*)d_in[2];
    const float* edge_w   = (const float*)d_in[3];
    const float* W1       = (const float*)d_in[4];
    const float* W2       = (const float*)d_in[5];
    const float* mlp_w1   = (const float*)d_in[6];
    const float* mlp_b1   = (const float*)d_in[7];
    const float* mlp_w2   = (const float*)d_in[8];
    const float* mlp_b2   = (const float*)d_in[9];
    float* out = (float*)d_out;

    void* pv;
    cudaGetSymbolAddress(&pv, g_B3);  float*  B3  = (float*)pv;
    cudaGetSymbolAddress(&pv, g_Ah1); __half* Ah1 = (__half*)pv;
    cudaGetSymbolAddress(&pv, g_Al1); __half* Al1 = (__half*)pv;
    cudaGetSymbolAddress(&pv, g_Ah2); __half* Ah2 = (__half*)pv;
    cudaGetSymbolAddress(&pv, g_Al2); __half* Al2 = (__half*)pv;
    cudaGetSymbolAddress(&pv, g_W1h); __half* W1h = (__half*)pv;
    cudaGetSymbolAddress(&pv, g_W1l); __half* W1l = (__half*)pv;
    cudaGetSymbolAddress(&pv, g_W2h); __half* W2h = (__half*)pv;
    cudaGetSymbolAddress(&pv, g_W2l); __half* W2l = (__half*)pv;
    cudaGetSymbolAddress(&pv, g_M1h); __half* M1h = (__half*)pv;
    cudaGetSymbolAddress(&pv, g_M1l); __half* M1l = (__half*)pv;
    cudaGetSymbolAddress(&pv, g_M2h); __half* M2h = (__half*)pv;
    cudaGetSymbolAddress(&pv, g_M2l); __half* M2l = (__half*)pv;

    const int SMEM_BYTES = 2 * STG_SZ;   // 131072
    cudaFuncSetAttribute(k_hgemm, cudaFuncAttributeMaxDynamicSharedMemorySize, SMEM_BYTES);

    const int E_BLKS = (EE + 255) / 256;
    const int N_BLKS = (NN + 255) / 256;
    const int SPMM_BLKS = (NN * 32 + 255) / 256;
    const int MT = (NN + 127) / 128;   // 391

    // CSR build by destination
    k_clear_cnt<<<N_BLKS, 256>>>();
    k_hist<<<E_BLKS, 256>>>(edge_dst);
    k_scan<<<1, 1024>>>();
    k_scatter<<<E_BLKS, 256>>>(edge_src, edge_dst, edge_w);

    // weight conversions (tiny)
    k_cvt_w<<<(256*256 + 255)/256, 256>>>(W1,     W1h, W1l, 256);
    k_cvt_w<<<(128*256 + 255)/256, 256>>>(W2,     W2h, W2l, 128);
    k_cvt_w<<<(256*256 + 255)/256, 256>>>(mlp_w1, M1h, M1l, 256);
    k_cvt_w<<<(128*256 + 255)/256, 256>>>(mlp_w2, M2h, M2l, 128);

    // t1 = A @ X  -> split fp16 (Ah1, Al1)
    k_spmm256<<<SPMM_BLKS, 256>>>(features, Ah1, Al1);

    // h1 = relu(t1 @ W1) -> out[:,128:384] fp32  AND  (Ah2, Al2) fp16 split
    {
        dim3 grid(2, MT);
        k_hgemm<<<grid, 256, SMEM_BYTES>>>(Ah1, Al1, W1h, W1l, nullptr,
                                           out + 128, 512, Ah2, Al2, NN, 1);
    }
    // g = h1 @ W2 -> B3 fp32   (reassociation: A@(h1@W2))
    {
        dim3 grid(1, MT);
        k_hgemm<<<grid, 256, SMEM_BYTES>>>(Ah2, Al2, W2h, W2l, nullptr,
                                           B3, 128, nullptr, nullptr, NN, 0);
    }
    // h2 = A @ g -> out[:,384:512]
    k_spmm128<<<SPMM_BLKS, 256>>>(B3, out + 384, 512);

    // features -> split fp16 (reuse Ah1/Al1)
    k_cvt_feat<<<(NN*64 + 255)/256, 256>>>((const float4*)features, Ah1, Al1);

    // hidden = relu(X @ mlp_w1 + b1) -> (Ah2, Al2) fp16 split only
    {
        dim3 grid(2, MT);
        k_hgemm<<<grid, 256, SMEM_BYTES>>>(Ah1, Al1, M1h, M1l, mlp_b1,
                                           nullptr, 0, Ah2, Al2, NN, 1);
    }
    // self_out = hidden @ mlp_w2 + b2 -> out[:,0:128]
    {
        dim3 grid(1, MT);
        k_hgemm<<<grid, 256, SMEM_BYTES>>>(Ah2, Al2, M2h, M2l, mlp_b2,
                                           out, 512, nullptr, nullptr, NN, 0);
    }
    (void)in_sizes; (void)n_in; (void)out_size;
}

// round 8
// speedup vs baseline: 2.4145x; 1.3721x over previous
#include <cuda_runtime.h>
#include <cuda_fp16.h>
#include <cstdint>

#define NN   50000
#define EE   800000
#define IN_F 256
#define HID_F 256
#define OUT_F 128

// ---------------- static device scratch (no allocation allowed) ----------------
__device__ int   g_cnt[NN];
__device__ int   g_rowptr[NN + 1];
__device__ int   g_cursor[NN];
__device__ int   g_srt_src[EE];
__device__ float g_srt_w[EE];
__device__ float g_B3[NN * 128];      // h1 @ W2 (pre-spmm2), fp32

// fp16 activation buffers (hi-only representation)
__device__ __half g_F16[NN * 256];    // features, fp16
__device__ __half g_T1[NN * 256];     // A @ X, fp16
__device__ __half g_H1[NN * 256];     // h1, fp16
__device__ __half g_HID[NN * 256];    // MLP hidden, fp16

// fp16 split transposed weights  B[n][k] = W[k][n]  (hi + lo, full precision)
__device__ __half g_W1h[256 * 256], g_W1l[256 * 256];
__device__ __half g_W2h[128 * 256], g_W2l[128 * 256];
__device__ __half g_M1h[256 * 256], g_M1l[256 * 256];
__device__ __half g_M2h[128 * 256], g_M2l[128 * 256];

// ---------------- PTX helpers (sm_80-era only: cp.async, ldmatrix, mma.sync) ----
__device__ __forceinline__ uint32_t smem_u32(const void* p) {
    uint32_t a;
    asm("{ .reg .u64 t; cvta.to.shared.u64 t, %1; cvt.u32.u64 %0, t; }" : "=r"(a) : "l"(p));
    return a;
}
__device__ __forceinline__ void cp16(uint32_t d, const void* s) {
    asm volatile("cp.async.cg.shared.global [%0], [%1], 16;" :: "r"(d), "l"(s) : "memory");
}
#define CP_COMMIT() asm volatile("cp.async.commit_group;" ::: "memory")
#define CP_WAIT(n)  asm volatile("cp.async.wait_group %0;" :: "n"(n) : "memory")

#define LDSM4(r0, r1, r2, r3, a) \
    asm volatile("ldmatrix.sync.aligned.m8n8.x4.shared.b16 {%0,%1,%2,%3}, [%4];" \
                 : "=r"(r0), "=r"(r1), "=r"(r2), "=r"(r3) : "r"(a))

#define MMA16816(c, a, b) \
    asm volatile("mma.sync.aligned.m16n8k16.row.col.f32.f16.f16.f32 " \
                 "{%0,%1,%2,%3}, {%4,%5,%6,%7}, {%8,%9}, {%0,%1,%2,%3};" \
                 : "+f"((c)[0]), "+f"((c)[1]), "+f"((c)[2]), "+f"((c)[3]) \
                 : "r"((a)[0]), "r"((a)[1]), "r"((a)[2]), "r"((a)[3]), \
                   "r"((b)[0]), "r"((b)[1]))

__device__ __forceinline__ uint32_t swz(uint32_t o) { return o ^ ((o >> 3) & 0x70); }

// ---------------- CSR build ----------------
__global__ void k_clear_cnt() {
    int i = blockIdx.x * blockDim.x + threadIdx.x;
    if (i < NN) g_cnt[i] = 0;
}

__global__ void k_hist(const int* __restrict__ dst) {
    int e = blockIdx.x * blockDim.x + threadIdx.x;
    if (e < EE) atomicAdd(&g_cnt[dst[e]], 1);
}

__global__ void k_scan() {
    __shared__ int warp_sums[32];
    int t = threadIdx.x;
    int lane = t & 31, wid = t >> 5;
    int carry = 0;
    for (int base = 0; base < NN; base += 1024) {
        int i = base + t;
        int v = (i < NN) ? g_cnt[i] : 0;
        int x = v;
        #pragma unroll
        for (int o = 1; o < 32; o <<= 1) {
            int y = __shfl_up_sync(0xFFFFFFFFu, x, o);
            if (lane >= o) x += y;
        }
        if (lane == 31) warp_sums[wid] = x;
        __syncthreads();
        if (wid == 0) {
            int s = warp_sums[lane];
            #pragma unroll
            for (int o = 1; o < 32; o <<= 1) {
                int y = __shfl_up_sync(0xFFFFFFFFu, s, o);
                if (lane >= o) s += y;
            }
            warp_sums[lane] = s;
        }
        __syncthreads();
        int warp_off = (wid == 0) ? 0 : warp_sums[wid - 1];
        int excl = carry + warp_off + x - v;
        if (i < NN) { g_rowptr[i] = excl; g_cursor[i] = excl; }
        int tot = warp_sums[31];
        __syncthreads();
        carry += tot;
    }
    if (t == 0) g_rowptr[NN] = carry;
}

__global__ void k_scatter(const int* __restrict__ src, const int* __restrict__ dst,
                          const float* __restrict__ w) {
    int e = blockIdx.x * blockDim.x + threadIdx.x;
    if (e < EE) {
        int p = atomicAdd(&g_cursor[dst[e]], 1);
        g_srt_src[p] = src[e];
        g_srt_w[p]   = w[e];
    }
}

// ---------------- gather SpMM over fp16 source (warp per dst node) -------------
// y[dst] = sum w * x16[src], fp32 accum, fp16 out. Lane handles 8 contiguous cols.
__global__ __launch_bounds__(256) void k_spmm256h(const __half* __restrict__ x16,
                                                  __half* __restrict__ y16) {
    int gw = (blockIdx.x * blockDim.x + threadIdx.x) >> 5;
    if (gw >= NN) return;
    int lane = threadIdx.x & 31;
    float a[8];
    #pragma unroll
    for (int i = 0; i < 8; i++) a[i] = 0.f;
    int s = g_rowptr[gw], e = g_rowptr[gw + 1];
    for (int i = s; i < e; i++) {
        int   src = g_srt_src[i];
        float w   = g_srt_w[i];
        uint4 v = *(const uint4*)(x16 + (size_t)src * 256 + lane * 8);
        const __half2* h = (const __half2*)&v;
        #pragma unroll
        for (int j = 0; j < 4; j++) {
            float2 f = __half22float2(h[j]);
            a[2*j + 0] += w * f.x;
            a[2*j + 1] += w * f.y;
        }
    }
    uint4 o;
    __half2* oh = (__half2*)&o;
    #pragma unroll
    for (int j = 0; j < 4; j++)
        oh[j] = __floats2half2_rn(a[2*j], a[2*j + 1]);
    *(uint4*)(y16 + (size_t)gw * 256 + lane * 8) = o;
}

// fp32 gather SpMM for the final hop (precision-critical: feeds output directly)
__global__ __launch_bounds__(256) void k_spmm128(const float* __restrict__ x,
                                                 float* __restrict__ y, int ldy) {
    int gw = (blockIdx.x * blockDim.x + threadIdx.x) >> 5;
    if (gw >= NN) return;
    int lane = threadIdx.x & 31;
    float4 a0 = make_float4(0.f, 0.f, 0.f, 0.f);
    int s = g_rowptr[gw], e = g_rowptr[gw + 1];
    for (int i = s; i < e; i++) {
        int   src = g_srt_src[i];
        float w   = g_srt_w[i];
        const float4* p = (const float4*)(x + (size_t)src * 128) + lane;
        float4 u = p[0];
        a0.x += w * u.x; a0.y += w * u.y; a0.z += w * u.z; a0.w += w * u.w;
    }
    float4* o = (float4*)(y + (size_t)gw * ldy) + lane;
    o[0] = a0;
}

// ---------------- conversion kernels ----------------
__global__ void k_cvt_w(const float* __restrict__ W, __half* __restrict__ bh,
                        __half* __restrict__ bl, int Nn) {
    int i = blockIdx.x * blockDim.x + threadIdx.x;
    if (i >= Nn * 256) return;
    int n = i >> 8, k = i & 255;
    float x = W[k * Nn + n];
    __half h = __float2half_rn(x);
    bh[i] = h;
    bl[i] = __float2half_rn(x - __half2float(h));
}

__global__ void k_cvt_feat(const float4* __restrict__ f, __half* __restrict__ y) {
    int i = blockIdx.x * blockDim.x + threadIdx.x;
    if (i >= NN * 64) return;
    float4 v = f[i];
    __half2* o = (__half2*)(y + (size_t)i * 4);
    o[0] = __floats2half2_rn(v.x, v.y);
    o[1] = __floats2half2_rn(v.z, v.w);
}

// ---------------- 2-product split GEMM on mma.sync ----------------
// D[128,128-tile] = Ah[M,256] @ (Bh+Bl)[Ntile,256]^T, fp32 accum.
// K chunks of 64 halves, 2-stage cp.async, 2 CTAs/SM.
// Stage layout (SW128 swizzled, 128B rows): +0 Ah, +16384 Bh, +32768 Bl.
#define STG_SZ 49152

__global__ __launch_bounds__(256, 2) void k_hgemm(
    const __half* __restrict__ A,
    const __half* __restrict__ Bh, const __half* __restrict__ Bl,
    const float* __restrict__ bias,
    float* __restrict__ C, int ldc,
    __half* __restrict__ Ch,
    int M, int relu)
{
    extern __shared__ char smem[];
    uint32_t sb = smem_u32(smem);

    int t    = threadIdx.x;
    int lane = t & 31;
    int wid  = t >> 5;
    int wm   = wid & 3;          // 4 warps along M (32 rows each)
    int wn   = wid >> 2;         // 2 warps along N (64 cols each)
    int bm   = blockIdx.y * 128;
    int bn   = blockIdx.x * 128;

    float acc[2][8][4];
    #pragma unroll
    for (int i = 0; i < 2; i++)
        #pragma unroll
        for (int j = 0; j < 8; j++)
            #pragma unroll
            for (int q = 0; q < 4; q++) acc[i][j][q] = 0.f;

    // 3 buffers x 128 rows x 8 chunks(16B) = 3072 cp16; 256 thr x 4 iters x 3
    auto LOADC = [&](int c) {
        uint32_t st = sb + (c & 1) * STG_SZ;
        #pragma unroll
        for (int i = 0; i < 4; i++) {
            int id  = t + 256 * i;
            int row = id >> 3;
            int c16 = id & 7;
            uint32_t s = swz((uint32_t)row * 128 + c16 * 16);
            int ar = bm + row; if (ar >= M) ar = M - 1;
            size_t ga = (size_t)ar * 256 + c * 64 + c16 * 8;
            size_t gb = (size_t)(bn + row) * 256 + c * 64 + c16 * 8;
            cp16(st +         s, A  + ga);
            cp16(st + 16384 + s, Bh + gb);
            cp16(st + 32768 + s, Bl + gb);
        }
        CP_COMMIT();
    };

    auto COMPUTE = [&](int c) {
        uint32_t st  = sb + (c & 1) * STG_SZ;
        uint32_t bA = st, bBh = st + 16384, bBl = st + 32768;
        #pragma unroll
        for (int ks = 0; ks < 4; ks++) {
            uint32_t ah[2][4], bh[8][2], bl[8][2];
            #pragma unroll
            for (int i = 0; i < 2; i++) {
                uint32_t o = swz(((uint32_t)(wm * 32 + i * 16 + (lane & 15)) << 7)
                                 + ks * 32 + ((lane >> 4) << 4));
                LDSM4(ah[i][0], ah[i][1], ah[i][2], ah[i][3], bA + o);
            }
            #pragma unroll
            for (int j = 0; j < 8; j += 2) {
                uint32_t o = swz(((uint32_t)(wn * 64 + (j + (lane >> 4)) * 8 + (lane & 7)) << 7)
                                 + ks * 32 + (((lane >> 3) & 1) << 4));
                LDSM4(bh[j][0], bh[j][1], bh[j+1][0], bh[j+1][1], bBh + o);
                LDSM4(bl[j][0], bl[j][1], bl[j+1][0], bl[j+1][1], bBl + o);
            }
            #pragma unroll
            for (int i = 0; i < 2; i++)
                #pragma unroll
                for (int j = 0; j < 8; j++) {
                    MMA16816(acc[i][j], ah[i], bh[j]);
                    MMA16816(acc[i][j], ah[i], bl[j]);
                }
        }
    };

    LOADC(0);
    LOADC(1);

    #pragma unroll
    for (int c = 0; c < 4; c++) {
        if (c < 3) { CP_WAIT(1); } else { CP_WAIT(0); }
        __syncthreads();
        COMPUTE(c);
        __syncthreads();
        if (c + 2 < 4) LOADC(c + 2);
    }

    // -------- epilogue: c-frag layout m16n8 --------
    int gid = lane >> 2;               // 0..7
    int qid = lane & 3;                // 0..3
    #pragma unroll
    for (int i = 0; i < 2; i++) {
        #pragma unroll
        for (int j = 0; j < 8; j++) {
            int col = bn + wn * 64 + j * 8 + qid * 2;
            float b0 = 0.f, b1 = 0.f;
            if (bias) { b0 = bias[col]; b1 = bias[col + 1]; }
            #pragma unroll
            for (int h = 0; h < 2; h++) {
                int gm = bm + wm * 32 + i * 16 + gid + h * 8;
                if (gm >= M) continue;
                float v0 = acc[i][j][2*h + 0] + b0;
                float v1 = acc[i][j][2*h + 1] + b1;
                if (relu) { v0 = fmaxf(v0, 0.f); v1 = fmaxf(v1, 0.f); }
                if (C) *(float2*)(C + (size_t)gm * ldc + col) = make_float2(v0, v1);
                if (Ch) *(__half2*)(Ch + (size_t)gm * 256 + col) = __floats2half2_rn(v0, v1);
            }
        }
    }
}

// ---------------- launch ----------------
extern "C" void kernel_launch(void* const* d_in, const int* in_sizes, int n_in,
                              void* d_out, int out_size) {
    const float* features = (const float*)d_in[0];
    const int*   edge_src = (const int*)d_in[1];
    const int*   edge_dst = (const int*)d_in[2];
    const float* edge_w   = (const float*)d_in[3];
    const float* W1       = (const float*)d_in[4];
    const float* W2       = (const float*)d_in[5];
    const float* mlp_w1   = (const float*)d_in[6];
    const float* mlp_b1   = (const float*)d_in[7];
    const float* mlp_w2   = (const float*)d_in[8];
    const float* mlp_b2   = (const float*)d_in[9];
    float* out = (float*)d_out;

    void* pv;
    cudaGetSymbolAddress(&pv, g_B3);  float*  B3  = (float*)pv;
    cudaGetSymbolAddress(&pv, g_F16); __half* F16 = (__half*)pv;
    cudaGetSymbolAddress(&pv, g_T1);  __half* T1  = (__half*)pv;
    cudaGetSymbolAddress(&pv, g_H1);  __half* H1  = (__half*)pv;
    cudaGetSymbolAddress(&pv, g_HID); __half* HID = (__half*)pv;
    cudaGetSymbolAddress(&pv, g_W1h); __half* W1h = (__half*)pv;
    cudaGetSymbolAddress(&pv, g_W1l); __half* W1l = (__half*)pv;
    cudaGetSymbolAddress(&pv, g_W2h); __half* W2h = (__half*)pv;
    cudaGetSymbolAddress(&pv, g_W2l); __half* W2l = (__half*)pv;
    cudaGetSymbolAddress(&pv, g_M1h); __half* M1h = (__half*)pv;
    cudaGetSymbolAddress(&pv, g_M1l); __half* M1l = (__half*)pv;
    cudaGetSymbolAddress(&pv, g_M2h); __half* M2h = (__half*)pv;
    cudaGetSymbolAddress(&pv, g_M2l); __half* M2l = (__half*)pv;

    const int SMEM_BYTES = 2 * STG_SZ;   // 98304 per CTA, 2 CTAs/SM
    cudaFuncSetAttribute(k_hgemm, cudaFuncAttributeMaxDynamicSharedMemorySize, SMEM_BYTES);

    const int E_BLKS = (EE + 255) / 256;
    const int N_BLKS = (NN + 255) / 256;
    const int SPMM_BLKS = (NN * 32 + 255) / 256;
    const int MT = (NN + 127) / 128;   // 391

    // CSR build by destination
    k_clear_cnt<<<N_BLKS, 256>>>();
    k_hist<<<E_BLKS, 256>>>(edge_dst);
    k_scan<<<1, 1024>>>();
    k_scatter<<<E_BLKS, 256>>>(edge_src, edge_dst, edge_w);

    // weight conversions (tiny) + feature fp16
    k_cvt_w<<<(256*256 + 255)/256, 256>>>(W1,     W1h, W1l, 256);
    k_cvt_w<<<(128*256 + 255)/256, 256>>>(W2,     W2h, W2l, 128);
    k_cvt_w<<<(256*256 + 255)/256, 256>>>(mlp_w1, M1h, M1l, 256);
    k_cvt_w<<<(128*256 + 255)/256, 256>>>(mlp_w2, M2h, M2l, 128);
    k_cvt_feat<<<(NN*64 + 255)/256, 256>>>((const float4*)features, F16);

    // t1 = A @ X   (fp16 gather, fp32 accum) -> T1 fp16
    k_spmm256h<<<SPMM_BLKS, 256>>>(F16, T1);

    // h1 = relu(t1 @ W1) -> out[:,128:384] fp32 AND H1 fp16
    {
        dim3 grid(2, MT);
        k_hgemm<<<grid, 256, SMEM_BYTES>>>(T1, W1h, W1l, nullptr,
                                           out + 128, 512, H1, NN, 1);
    }
    // g = h1 @ W2 -> B3 fp32   (reassociation: A@(h1@W2))
    {
        dim3 grid(1, MT);
        k_hgemm<<<grid, 256, SMEM_BYTES>>>(H1, W2h, W2l, nullptr,
                                           B3, 128, nullptr, NN, 0);
    }
    // h2 = A @ g -> out[:,384:512]  (fp32 gather)
    k_spmm128<<<SPMM_BLKS, 256>>>(B3, out + 384, 512);

    // hidden = relu(X @ mlp_w1 + b1) -> HID fp16
    {
        dim3 grid(2, MT);
        k_hgemm<<<grid, 256, SMEM_BYTES>>>(F16, M1h, M1l, mlp_b1,
                                           nullptr, 0, HID, NN, 1);
    }
    // self_out = hidden @ mlp_w2 + b2 -> out[:,0:128]
    {
        dim3 grid(1, MT);
        k_hgemm<<<grid, 256, SMEM_BYTES>>>(HID, M2h, M2l, mlp_b2,
                                           out, 512, nullptr, NN, 0);
    }
    (void)in_sizes; (void)n_in; (void)out_size;
}

// round 12
// speedup vs baseline: 2.9743x; 1.2318x over previous
#include <cuda_runtime.h>
#include <cuda_fp16.h>
#include <cstdint>

#define NN   50000
#define EE   800000
#define IN_F 256
#define HID_F 256
#define OUT_F 128

// ---------------- static device scratch (no allocation allowed) ----------------
__device__ int   g_cnt[NN];
__device__ int   g_rowptr[NN + 1];
__device__ int   g_cursor[NN];
__device__ int   g_srt_src[EE];
__device__ float g_srt_w[EE];

// fp16 activation buffers (hi-only representation)
__device__ __half g_F16[NN * 256];    // features, fp16
__device__ __half g_T1[NN * 256];     // A @ X, fp16
__device__ __half g_H1[NN * 256];     // h1, fp16
__device__ __half g_HID[NN * 256];    // MLP hidden, fp16
__device__ __half g_B3h[NN * 128];    // h1 @ W2 (pre-spmm2), fp16

// fp16 transposed weights  B[n][k] = W[k][n]  (hi only)
__device__ __half g_W1h[256 * 256];
__device__ __half g_W2h[128 * 256];
__device__ __half g_M1h[256 * 256];
__device__ __half g_M2h[128 * 256];

// ---------------- PTX helpers (sm_80-era only: cp.async, ldmatrix, mma.sync) ----
__device__ __forceinline__ uint32_t smem_u32(const void* p) {
    uint32_t a;
    asm("{ .reg .u64 t; cvta.to.shared.u64 t, %1; cvt.u32.u64 %0, t; }" : "=r"(a) : "l"(p));
    return a;
}
__device__ __forceinline__ void cp16(uint32_t d, const void* s) {
    asm volatile("cp.async.cg.shared.global [%0], [%1], 16;" :: "r"(d), "l"(s) : "memory");
}
#define CP_COMMIT() asm volatile("cp.async.commit_group;" ::: "memory")
#define CP_WAIT(n)  asm volatile("cp.async.wait_group %0;" :: "n"(n) : "memory")

#define LDSM4(r0, r1, r2, r3, a) \
    asm volatile("ldmatrix.sync.aligned.m8n8.x4.shared.b16 {%0,%1,%2,%3}, [%4];" \
                 : "=r"(r0), "=r"(r1), "=r"(r2), "=r"(r3) : "r"(a))

#define MMA16816(c, a, b) \
    asm volatile("mma.sync.aligned.m16n8k16.row.col.f32.f16.f16.f32 " \
                 "{%0,%1,%2,%3}, {%4,%5,%6,%7}, {%8,%9}, {%0,%1,%2,%3};" \
                 : "+f"((c)[0]), "+f"((c)[1]), "+f"((c)[2]), "+f"((c)[3]) \
                 : "r"((a)[0]), "r"((a)[1]), "r"((a)[2]), "r"((a)[3]), \
                   "r"((b)[0]), "r"((b)[1]))

__device__ __forceinline__ uint32_t swz(uint32_t o) { return o ^ ((o >> 3) & 0x70); }

// ---------------- CSR build ----------------
__global__ void k_clear_cnt() {
    int i = blockIdx.x * blockDim.x + threadIdx.x;
    if (i < NN) g_cnt[i] = 0;
}

__global__ void k_hist(const int* __restrict__ dst) {
    int e = blockIdx.x * blockDim.x + threadIdx.x;
    if (e < EE) atomicAdd(&g_cnt[dst[e]], 1);
}

__global__ void k_scan() {
    __shared__ int warp_sums[32];
    int t = threadIdx.x;
    int lane = t & 31, wid = t >> 5;
    int carry = 0;
    for (int base = 0; base < NN; base += 1024) {
        int i = base + t;
        int v = (i < NN) ? g_cnt[i] : 0;
        int x = v;
        #pragma unroll
        for (int o = 1; o < 32; o <<= 1) {
            int y = __shfl_up_sync(0xFFFFFFFFu, x, o);
            if (lane >= o) x += y;
        }
        if (lane == 31) warp_sums[wid] = x;
        __syncthreads();
        if (wid == 0) {
            int s = warp_sums[lane];
            #pragma unroll
            for (int o = 1; o < 32; o <<= 1) {
                int y = __shfl_up_sync(0xFFFFFFFFu, s, o);
                if (lane >= o) s += y;
            }
            warp_sums[lane] = s;
        }
        __syncthreads();
        int warp_off = (wid == 0) ? 0 : warp_sums[wid - 1];
        int excl = carry + warp_off + x - v;
        if (i < NN) { g_rowptr[i] = excl; g_cursor[i] = excl; }
        int tot = warp_sums[31];
        __syncthreads();
        carry += tot;
    }
    if (t == 0) g_rowptr[NN] = carry;
}

__global__ void k_scatter(const int* __restrict__ src, const int* __restrict__ dst,
                          const float* __restrict__ w) {
    int e = blockIdx.x * blockDim.x + threadIdx.x;
    if (e < EE) {
        int p = atomicAdd(&g_cursor[dst[e]], 1);
        g_srt_src[p] = src[e];
        g_srt_w[p]   = w[e];
    }
}

// ---------------- gather SpMM over fp16 source (warp per dst node) -------------
// y16[dst] = sum w * x16[src], fp32 accum, fp16 out. Lane handles 8 contiguous cols.
__global__ __launch_bounds__(256) void k_spmm256h(const __half* __restrict__ x16,
                                                  __half* __restrict__ y16) {
    int gw = (blockIdx.x * blockDim.x + threadIdx.x) >> 5;
    if (gw >= NN) return;
    int lane = threadIdx.x & 31;
    float a[8];
    #pragma unroll
    for (int i = 0; i < 8; i++) a[i] = 0.f;
    int s = g_rowptr[gw], e = g_rowptr[gw + 1];
    for (int i = s; i < e; i++) {
        int   src = g_srt_src[i];
        float w   = g_srt_w[i];
        uint4 v = *(const uint4*)(x16 + (size_t)src * 256 + lane * 8);
        const __half2* h = (const __half2*)&v;
        #pragma unroll
        for (int j = 0; j < 4; j++) {
            float2 f = __half22float2(h[j]);
            a[2*j + 0] += w * f.x;
            a[2*j + 1] += w * f.y;
        }
    }
    uint4 o;
    __half2* oh = (__half2*)&o;
    #pragma unroll
    for (int j = 0; j < 4; j++)
        oh[j] = __floats2half2_rn(a[2*j], a[2*j + 1]);
    *(uint4*)(y16 + (size_t)gw * 256 + lane * 8) = o;
}

// fp16 gather SpMM for the final hop: fp32 accum, fp32 output (direct to out).
__global__ __launch_bounds__(256) void k_spmm128h(const __half* __restrict__ x16,
                                                  float* __restrict__ y, int ldy) {
    int gw = (blockIdx.x * blockDim.x + threadIdx.x) >> 5;
    if (gw >= NN) return;
    int lane = threadIdx.x & 31;
    float a[4];
    #pragma unroll
    for (int i = 0; i < 4; i++) a[i] = 0.f;
    int s = g_rowptr[gw], e = g_rowptr[gw + 1];
    for (int i = s; i < e; i++) {
        int   src = g_srt_src[i];
        float w   = g_srt_w[i];
        uint2 v = *(const uint2*)(x16 + (size_t)src * 128 + lane * 4);
        const __half2* h = (const __half2*)&v;
        #pragma unroll
        for (int j = 0; j < 2; j++) {
            float2 f = __half22float2(h[j]);
            a[2*j + 0] += w * f.x;
            a[2*j + 1] += w * f.y;
        }
    }
    *(float4*)(y + (size_t)gw * ldy + lane * 4) = make_float4(a[0], a[1], a[2], a[3]);
}

// ---------------- conversion kernels ----------------
__global__ void k_cvt_w(const float* __restrict__ W, __half* __restrict__ bh, int Nn) {
    int i = blockIdx.x * blockDim.x + threadIdx.x;
    if (i >= Nn * 256) return;
    int n = i >> 8, k = i & 255;
    bh[i] = __float2half_rn(W[k * Nn + n]);
}

__global__ void k_cvt_feat(const float4* __restrict__ f, __half* __restrict__ y) {
    int i = blockIdx.x * blockDim.x + threadIdx.x;
    if (i >= NN * 64) return;
    float4 v = f[i];
    __half2* o = (__half2*)(y + (size_t)i * 4);
    o[0] = __floats2half2_rn(v.x, v.y);
    o[1] = __floats2half2_rn(v.z, v.w);
}

// ---------------- plain fp16 GEMM on mma.sync (fp32 accum) ----------------
// D[128,128-tile] = A[M,256] @ B[Ntile,256]^T. K chunks of 64 halves, 2-stage.
// Stage layout (SW128 swizzled, 128B rows): +0 A (16KB), +16384 B (16KB).
#define STG_SZ 32768

__global__ __launch_bounds__(256, 2) void k_hgemm(
    const __half* __restrict__ A,
    const __half* __restrict__ B,
    const float* __restrict__ bias,
    float* __restrict__ C, int ldc,
    __half* __restrict__ Ch, int ldch,
    int M, int relu)
{
    extern __shared__ char smem[];
    uint32_t sb = smem_u32(smem);

    int t    = threadIdx.x;
    int lane = t & 31;
    int wid  = t >> 5;
    int wm   = wid & 3;          // 4 warps along M (32 rows each)
    int wn   = wid >> 2;         // 2 warps along N (64 cols each)
    int bm   = blockIdx.y * 128;
    int bn   = blockIdx.x * 128;

    float acc[2][8][4];
    #pragma unroll
    for (int i = 0; i < 2; i++)
        #pragma unroll
        for (int j = 0; j < 8; j++)
            #pragma unroll
            for (int q = 0; q < 4; q++) acc[i][j][q] = 0.f;

    // 2 buffers x 128 rows x 8 chunks(16B) = 2048 cp16; 256 thr x 4 iters x 2
    auto LOADC = [&](int c) {
        uint32_t st = sb + (c & 1) * STG_SZ;
        #pragma unroll
        for (int i = 0; i < 4; i++) {
            int id  = t + 256 * i;
            int row = id >> 3;
            int c16 = id & 7;
            uint32_t s = swz((uint32_t)row * 128 + c16 * 16);
            int ar = bm + row; if (ar >= M) ar = M - 1;
            size_t ga = (size_t)ar * 256 + c * 64 + c16 * 8;
            size_t gb = (size_t)(bn + row) * 256 + c * 64 + c16 * 8;
            cp16(st +         s, A + ga);
            cp16(st + 16384 + s, B + gb);
        }
        CP_COMMIT();
    };

    auto COMPUTE = [&](int c) {
        uint32_t st = sb + (c & 1) * STG_SZ;
        uint32_t bA = st, bB = st + 16384;
        #pragma unroll
        for (int ks = 0; ks < 4; ks++) {
            uint32_t ah[2][4], bh[8][2];
            #pragma unroll
            for (int i = 0; i < 2; i++) {
                uint32_t o = swz(((uint32_t)(wm * 32 + i * 16 + (lane & 15)) << 7)
                                 + ks * 32 + ((lane >> 4) << 4));
                LDSM4(ah[i][0], ah[i][1], ah[i][2], ah[i][3], bA + o);
            }
            #pragma unroll
            for (int j = 0; j < 8; j += 2) {
                uint32_t o = swz(((uint32_t)(wn * 64 + (j + (lane >> 4)) * 8 + (lane & 7)) << 7)
                                 + ks * 32 + (((lane >> 3) & 1) << 4));
                LDSM4(bh[j][0], bh[j][1], bh[j+1][0], bh[j+1][1], bB + o);
            }
            #pragma unroll
            for (int i = 0; i < 2; i++)
                #pragma unroll
                for (int j = 0; j < 8; j++)
                    MMA16816(acc[i][j], ah[i], bh[j]);
        }
    };

    LOADC(0);
    LOADC(1);

    #pragma unroll
    for (int c = 0; c < 4; c++) {
        if (c < 3) { CP_WAIT(1); } else { CP_WAIT(0); }
        __syncthreads();
        COMPUTE(c);
        __syncthreads();
        if (c + 2 < 4) LOADC(c + 2);
    }

    // -------- epilogue: c-frag layout m16n8 --------
    int gid = lane >> 2;               // 0..7
    int qid = lane & 3;                // 0..3
    #pragma unroll
    for (int i = 0; i < 2; i++) {
        #pragma unroll
        for (int j = 0; j < 8; j++) {
            int col = bn + wn * 64 + j * 8 + qid * 2;
            float b0 = 0.f, b1 = 0.f;
            if (bias) { b0 = bias[col]; b1 = bias[col + 1]; }
            #pragma unroll
            for (int h = 0; h < 2; h++) {
                int gm = bm + wm * 32 + i * 16 + gid + h * 8;
                if (gm >= M) continue;
                float v0 = acc[i][j][2*h + 0] + b0;
                float v1 = acc[i][j][2*h + 1] + b1;
                if (relu) { v0 = fmaxf(v0, 0.f); v1 = fmaxf(v1, 0.f); }
                if (C) *(float2*)(C + (size_t)gm * ldc + col) = make_float2(v0, v1);
                if (Ch) *(__half2*)(Ch + (size_t)gm * ldch + col) = __floats2half2_rn(v0, v1);
            }
        }
    }
}

// ---------------- launch ----------------
extern "C" void kernel_launch(void* const* d_in, const int* in_sizes, int n_in,
                              void* d_out, int out_size) {
    const float* features = (const float*)d_in[0];
    const int*   edge_src = (const int*)d_in[1];
    const int*   edge_dst = (const int*)d_in[2];
    const float* edge_w   = (const float*)d_in[3];
    const float* W1       = (const float*)d_in[4];
    const float* W2       = (const float*)d_in[5];
    const float* mlp_w1   = (const float*)d_in[6];
    const float* mlp_b1   = (const float*)d_in[7];
    const float* mlp_w2   = (const float*)d_in[8];
    const float* mlp_b2   = (const float*)d_in[9];
    float* out = (float*)d_out;

    void* pv;
    cudaGetSymbolAddress(&pv, g_F16); __half* F16 = (__half*)pv;
    cudaGetSymbolAddress(&pv, g_T1);  __half* T1  = (__half*)pv;
    cudaGetSymbolAddress(&pv, g_H1);  __half* H1  = (__half*)pv;
    cudaGetSymbolAddress(&pv, g_HID); __half* HID = (__half*)pv;
    cudaGetSymbolAddress(&pv, g_B3h); __half* B3h = (__half*)pv;
    cudaGetSymbolAddress(&pv, g_W1h); __half* W1h = (__half*)pv;
    cudaGetSymbolAddress(&pv, g_W2h); __half* W2h = (__half*)pv;
    cudaGetSymbolAddress(&pv, g_M1h); __half* M1h = (__half*)pv;
    cudaGetSymbolAddress(&pv, g_M2h); __half* M2h = (__half*)pv;

    const int SMEM_BYTES = 2 * STG_SZ;   // 65536 per CTA, 2 CTAs/SM
    cudaFuncSetAttribute(k_hgemm, cudaFuncAttributeMaxDynamicSharedMemorySize, SMEM_BYTES);

    const int E_BLKS = (EE + 255) / 256;
    const int N_BLKS = (NN + 255) / 256;
    const int SPMM_BLKS = (NN * 32 + 255) / 256;
    const int MT = (NN + 127) / 128;   // 391

    // CSR build by destination
    k_clear_cnt<<<N_BLKS, 256>>>();
    k_hist<<<E_BLKS, 256>>>(edge_dst);
    k_scan<<<1, 1024>>>();
    k_scatter<<<E_BLKS, 256>>>(edge_src, edge_dst, edge_w);

    // weight conversions (tiny, hi only) + feature fp16
    k_cvt_w<<<(256*256 + 255)/256, 256>>>(W1,     W1h, 256);
    k_cvt_w<<<(128*256 + 255)/256, 256>>>(W2,     W2h, 128);
    k_cvt_w<<<(256*256 + 255)/256, 256>>>(mlp_w1, M1h, 256);
    k_cvt_w<<<(128*256 + 255)/256, 256>>>(mlp_w2, M2h, 128);
    k_cvt_feat<<<(NN*64 + 255)/256, 256>>>((const float4*)features, F16);

    // t1 = A @ X   (fp16 gather, fp32 accum) -> T1 fp16
    k_spmm256h<<<SPMM_BLKS, 256>>>(F16, T1);

    // h1 = relu(t1 @ W1) -> out[:,128:384] fp32 AND H1 fp16
    {
        dim3 grid(2, MT);
        k_hgemm<<<grid, 256, SMEM_BYTES>>>(T1, W1h, nullptr,
                                           out + 128, 512, H1, 256, NN, 1);
    }
    // g = h1 @ W2 -> B3h fp16   (reassociation: A@(h1@W2))
    {
        dim3 grid(1, MT);
        k_hgemm<<<grid, 256, SMEM_BYTES>>>(H1, W2h, nullptr,
                                           nullptr, 0, B3h, 128, NN, 0);
    }
    // h2 = A @ g -> out[:,384:512]  (fp16 gather, fp32 accum/out)
    k_spmm128h<<<SPMM_BLKS, 256>>>(B3h, out + 384, 512);

    // hidden = relu(X @ mlp_w1 + b1) -> HID fp16
    {
        dim3 grid(2, MT);
        k_hgemm<<<grid, 256, SMEM_BYTES>>>(F16, M1h, mlp_b1,
                                           nullptr, 0, HID, 256, NN, 1);
    }
    // self_out = hidden @ mlp_w2 + b2 -> out[:,0:128]
    {
        dim3 grid(1, MT);
        k_hgemm<<<grid, 256, SMEM_BYTES>>>(HID, M2h, mlp_b2,
                                           out, 512, nullptr, 0, NN, 0);
    }
    (void)in_sizes; (void)n_in; (void)out_size;
}

// round 13
// speedup vs baseline: 3.6886x; 1.2401x over previous
#include <cuda_runtime.h>
#include <cuda_fp16.h>
#include <cstdint>

#define NN   50000
#define EE   800000
#define IN_F 256
#define HID_F 256
#define OUT_F 128

// ---------------- static device scratch (no allocation allowed) ----------------
__device__ int   g_cnt[NN];
__device__ int   g_rowptr[NN + 1];
__device__ int   g_cursor[NN];
__device__ int2  g_srt[EE];           // (src, weight-bits) interleaved

// fp16 activation buffers (hi-only representation)
__device__ __half g_F16[NN * 256];    // features, fp16
__device__ __half g_T1[NN * 256];     // A @ X, fp16
__device__ __half g_H1[NN * 256];     // h1, fp16
__device__ __half g_HID[NN * 256];    // MLP hidden, fp16
__device__ __half g_B3h[NN * 128];    // h1 @ W2 (pre-spmm2), fp16

// fp16 transposed weights  B[n][k] = W[k][n]  (hi only)
__device__ __half g_W1h[256 * 256];
__device__ __half g_W2h[128 * 256];
__device__ __half g_M1h[256 * 256];
__device__ __half g_M2h[128 * 256];

// ---------------- PTX helpers (sm_80-era only: cp.async, ldmatrix, mma.sync) ----
__device__ __forceinline__ uint32_t smem_u32(const void* p) {
    uint32_t a;
    asm("{ .reg .u64 t; cvta.to.shared.u64 t, %1; cvt.u32.u64 %0, t; }" : "=r"(a) : "l"(p));
    return a;
}
__device__ __forceinline__ void cp16(uint32_t d, const void* s) {
    asm volatile("cp.async.cg.shared.global [%0], [%1], 16;" :: "r"(d), "l"(s) : "memory");
}
#define CP_COMMIT() asm volatile("cp.async.commit_group;" ::: "memory")
#define CP_WAIT(n)  asm volatile("cp.async.wait_group %0;" :: "n"(n) : "memory")

#define LDSM4(r0, r1, r2, r3, a) \
    asm volatile("ldmatrix.sync.aligned.m8n8.x4.shared.b16 {%0,%1,%2,%3}, [%4];" \
                 : "=r"(r0), "=r"(r1), "=r"(r2), "=r"(r3) : "r"(a))

#define MMA16816(c, a, b) \
    asm volatile("mma.sync.aligned.m16n8k16.row.col.f32.f16.f16.f32 " \
                 "{%0,%1,%2,%3}, {%4,%5,%6,%7}, {%8,%9}, {%0,%1,%2,%3};" \
                 : "+f"((c)[0]), "+f"((c)[1]), "+f"((c)[2]), "+f"((c)[3]) \
                 : "r"((a)[0]), "r"((a)[1]), "r"((a)[2]), "r"((a)[3]), \
                   "r"((b)[0]), "r"((b)[1]))

__device__ __forceinline__ uint32_t swz(uint32_t o) { return o ^ ((o >> 3) & 0x70); }

// ---------------- CSR build ----------------
__global__ void k_clear_cnt() {
    int i = blockIdx.x * blockDim.x + threadIdx.x;
    if (i < NN) g_cnt[i] = 0;
}

__global__ void k_hist(const int* __restrict__ dst) {
    int e = blockIdx.x * blockDim.x + threadIdx.x;
    if (e < EE) atomicAdd(&g_cnt[dst[e]], 1);
}

__global__ void k_scan() {
    __shared__ int warp_sums[32];
    int t = threadIdx.x;
    int lane = t & 31, wid = t >> 5;
    int carry = 0;
    for (int base = 0; base < NN; base += 1024) {
        int i = base + t;
        int v = (i < NN) ? g_cnt[i] : 0;
        int x = v;
        #pragma unroll
        for (int o = 1; o < 32; o <<= 1) {
            int y = __shfl_up_sync(0xFFFFFFFFu, x, o);
            if (lane >= o) x += y;
        }
        if (lane == 31) warp_sums[wid] = x;
        __syncthreads();
        if (wid == 0) {
            int s = warp_sums[lane];
            #pragma unroll
            for (int o = 1; o < 32; o <<= 1) {
                int y = __shfl_up_sync(0xFFFFFFFFu, s, o);
                if (lane >= o) s += y;
            }
            warp_sums[lane] = s;
        }
        __syncthreads();
        int warp_off = (wid == 0) ? 0 : warp_sums[wid - 1];
        int excl = carry + warp_off + x - v;
        if (i < NN) { g_rowptr[i] = excl; g_cursor[i] = excl; }
        int tot = warp_sums[31];
        __syncthreads();
        carry += tot;
    }
    if (t == 0) g_rowptr[NN] = carry;
}

__global__ void k_scatter(const int* __restrict__ src, const int* __restrict__ dst,
                          const float* __restrict__ w) {
    int e = blockIdx.x * blockDim.x + threadIdx.x;
    if (e < EE) {
        int p = atomicAdd(&g_cursor[dst[e]], 1);
        g_srt[p] = make_int2(src[e], __float_as_int(w[e]));
    }
}

// ---------------- gather SpMM over fp16 source (warp per dst node) -------------
__global__ __launch_bounds__(256) void k_spmm256h(const __half* __restrict__ x16,
                                                  __half* __restrict__ y16) {
    int gw = (blockIdx.x * blockDim.x + threadIdx.x) >> 5;
    if (gw >= NN) return;
    int lane = threadIdx.x & 31;
    float a[8];
    #pragma unroll
    for (int i = 0; i < 8; i++) a[i] = 0.f;
    int s = g_rowptr[gw], e = g_rowptr[gw + 1];
    for (int i = s; i < e; i++) {
        int2  ew  = g_srt[i];
        float w   = __int_as_float(ew.y);
        uint4 v = *(const uint4*)(x16 + (size_t)ew.x * 256 + lane * 8);
        const __half2* h = (const __half2*)&v;
        #pragma unroll
        for (int j = 0; j < 4; j++) {
            float2 f = __half22float2(h[j]);
            a[2*j + 0] += w * f.x;
            a[2*j + 1] += w * f.y;
        }
    }
    uint4 o;
    __half2* oh = (__half2*)&o;
    #pragma unroll
    for (int j = 0; j < 4; j++)
        oh[j] = __floats2half2_rn(a[2*j], a[2*j + 1]);
    *(uint4*)(y16 + (size_t)gw * 256 + lane * 8) = o;
}

// fp16 gather SpMM for the final hop: fp32 accum, fp32 output (direct to out).
__global__ __launch_bounds__(256) void k_spmm128h(const __half* __restrict__ x16,
                                                  float* __restrict__ y, int ldy) {
    int gw = (blockIdx.x * blockDim.x + threadIdx.x) >> 5;
    if (gw >= NN) return;
    int lane = threadIdx.x & 31;
    float a[4];
    #pragma unroll
    for (int i = 0; i < 4; i++) a[i] = 0.f;
    int s = g_rowptr[gw], e = g_rowptr[gw + 1];
    for (int i = s; i < e; i++) {
        int2  ew  = g_srt[i];
        float w   = __int_as_float(ew.y);
        uint2 v = *(const uint2*)(x16 + (size_t)ew.x * 128 + lane * 4);
        const __half2* h = (const __half2*)&v;
        #pragma unroll
        for (int j = 0; j < 2; j++) {
            float2 f = __half22float2(h[j]);
            a[2*j + 0] += w * f.x;
            a[2*j + 1] += w * f.y;
        }
    }
    *(float4*)(y + (size_t)gw * ldy + lane * 4) = make_float4(a[0], a[1], a[2], a[3]);
}

// ---------------- conversion kernels ----------------
__global__ void k_cvt_w(const float* __restrict__ W, __half* __restrict__ bh, int Nn) {
    int i = blockIdx.x * blockDim.x + threadIdx.x;
    if (i >= Nn * 256) return;
    int n = i >> 8, k = i & 255;
    bh[i] = __float2half_rn(W[k * Nn + n]);
}

__global__ void k_cvt_feat(const float4* __restrict__ f, __half* __restrict__ y) {
    int i = blockIdx.x * blockDim.x + threadIdx.x;
    if (i >= NN * 64) return;
    float4 v = f[i];
    __half2* o = (__half2*)(y + (size_t)i * 4);
    o[0] = __floats2half2_rn(v.x, v.y);
    o[1] = __floats2half2_rn(v.z, v.w);
}

// ---------------- plain fp16 GEMM on mma.sync (fp32 accum) ----------------
// D[128,128-tile] = A[M,256] @ B[Ntile,256]^T. K chunks of 64 halves, 2-stage.
// Stage layout (SW128 swizzled, 128B rows): +0 A (16KB), +16384 B (16KB).
#define STG_SZ 32768

__global__ __launch_bounds__(256, 2) void k_hgemm(
    const __half* __restrict__ A,
    const __half* __restrict__ B,
    const float* __restrict__ bias,
    float* __restrict__ C, int ldc,
    __half* __restrict__ Ch, int ldch,
    int M, int relu)
{
    extern __shared__ char smem[];
    uint32_t sb = smem_u32(smem);

    int t    = threadIdx.x;
    int lane = t & 31;
    int wid  = t >> 5;
    int wm   = wid & 3;          // 4 warps along M (32 rows each)
    int wn   = wid >> 2;         // 2 warps along N (64 cols each)
    int bm   = blockIdx.y * 128;
    int bn   = blockIdx.x * 128;

    float acc[2][8][4];
    #pragma unroll
    for (int i = 0; i < 2; i++)
        #pragma unroll
        for (int j = 0; j < 8; j++)
            #pragma unroll
            for (int q = 0; q < 4; q++) acc[i][j][q] = 0.f;

    auto LOADC = [&](int c) {
        uint32_t st = sb + (c & 1) * STG_SZ;
        #pragma unroll
        for (int i = 0; i < 4; i++) {
            int id  = t + 256 * i;
            int row = id >> 3;
            int c16 = id & 7;
            uint32_t s = swz((uint32_t)row * 128 + c16 * 16);
            int ar = bm + row; if (ar >= M) ar = M - 1;
            size_t ga = (size_t)ar * 256 + c * 64 + c16 * 8;
            size_t gb = (size_t)(bn + row) * 256 + c * 64 + c16 * 8;
            cp16(st +         s, A + ga);
            cp16(st + 16384 + s, B + gb);
        }
        CP_COMMIT();
    };

    auto COMPUTE = [&](int c) {
        uint32_t st = sb + (c & 1) * STG_SZ;
        uint32_t bA = st, bB = st + 16384;
        #pragma unroll
        for (int ks = 0; ks < 4; ks++) {
            uint32_t ah[2][4], bh[8][2];
            #pragma unroll
            for (int i = 0; i < 2; i++) {
                uint32_t o = swz(((uint32_t)(wm * 32 + i * 16 + (lane & 15)) << 7)
                                 + ks * 32 + ((lane >> 4) << 4));
                LDSM4(ah[i][0], ah[i][1], ah[i][2], ah[i][3], bA + o);
            }
            #pragma unroll
            for (int j = 0; j < 8; j += 2) {
                uint32_t o = swz(((uint32_t)(wn * 64 + (j + (lane >> 4)) * 8 + (lane & 7)) << 7)
                                 + ks * 32 + (((lane >> 3) & 1) << 4));
                LDSM4(bh[j][0], bh[j][1], bh[j+1][0], bh[j+1][1], bB + o);
            }
            #pragma unroll
            for (int i = 0; i < 2; i++)
                #pragma unroll
                for (int j = 0; j < 8; j++)
                    MMA16816(acc[i][j], ah[i], bh[j]);
        }
    };

    LOADC(0);
    LOADC(1);

    #pragma unroll
    for (int c = 0; c < 4; c++) {
        if (c < 3) { CP_WAIT(1); } else { CP_WAIT(0); }
        __syncthreads();
        COMPUTE(c);
        __syncthreads();
        if (c + 2 < 4) LOADC(c + 2);
    }

    // -------- epilogue: c-frag layout m16n8 --------
    int gid = lane >> 2;
    int qid = lane & 3;
    #pragma unroll
    for (int i = 0; i < 2; i++) {
        #pragma unroll
        for (int j = 0; j < 8; j++) {
            int col = bn + wn * 64 + j * 8 + qid * 2;
            float b0 = 0.f, b1 = 0.f;
            if (bias) { b0 = bias[col]; b1 = bias[col + 1]; }
            #pragma unroll
            for (int h = 0; h < 2; h++) {
                int gm = bm + wm * 32 + i * 16 + gid + h * 8;
                if (gm >= M) continue;
                float v0 = acc[i][j][2*h + 0] + b0;
                float v1 = acc[i][j][2*h + 1] + b1;
                if (relu) { v0 = fmaxf(v0, 0.f); v1 = fmaxf(v1, 0.f); }
                if (C) *(float2*)(C + (size_t)gm * ldc + col) = make_float2(v0, v1);
                if (Ch) *(__half2*)(Ch + (size_t)gm * ldch + col) = __floats2half2_rn(v0, v1);
            }
        }
    }
}

// ---------------- launch ----------------
extern "C" void kernel_launch(void* const* d_in, const int* in_sizes, int n_in,
                              void* d_out, int out_size) {
    const float* features = (const float*)d_in[0];
    const int*   edge_src = (const int*)d_in[1];
    const int*   edge_dst = (const int*)d_in[2];
    const float* edge_w   = (const float*)d_in[3];
    const float* W1       = (const float*)d_in[4];
    const float* W2       = (const float*)d_in[5];
    const float* mlp_w1   = (const float*)d_in[6];
    const float* mlp_b1   = (const float*)d_in[7];
    const float* mlp_w2   = (const float*)d_in[8];
    const float* mlp_b2   = (const float*)d_in[9];
    float* out = (float*)d_out;

    void* pv;
    cudaGetSymbolAddress(&pv, g_F16); __half* F16 = (__half*)pv;
    cudaGetSymbolAddress(&pv, g_T1);  __half* T1  = (__half*)pv;
    cudaGetSymbolAddress(&pv, g_H1);  __half* H1  = (__half*)pv;
    cudaGetSymbolAddress(&pv, g_HID); __half* HID = (__half*)pv;
    cudaGetSymbolAddress(&pv, g_B3h); __half* B3h = (__half*)pv;
    cudaGetSymbolAddress(&pv, g_W1h); __half* W1h = (__half*)pv;
    cudaGetSymbolAddress(&pv, g_W2h); __half* W2h = (__half*)pv;
    cudaGetSymbolAddress(&pv, g_M1h); __half* M1h = (__half*)pv;
    cudaGetSymbolAddress(&pv, g_M2h); __half* M2h = (__half*)pv;

    const int SMEM_BYTES = 2 * STG_SZ;   // 65536 per CTA, 2 CTAs/SM
    cudaFuncSetAttribute(k_hgemm, cudaFuncAttributeMaxDynamicSharedMemorySize, SMEM_BYTES);

    const int E_BLKS = (EE + 255) / 256;
    const int N_BLKS = (NN + 255) / 256;
    const int SPMM_BLKS = (NN * 32 + 255) / 256;
    const int MT = (NN + 127) / 128;   // 391

    // -------- fork a second stream for the independent MLP branch --------
    cudaStream_t sB;
    cudaStreamCreateWithFlags(&sB, cudaStreamNonBlocking);
    cudaEvent_t evFork, evFeat, evB;
    cudaEventCreateWithFlags(&evFork, cudaEventDisableTiming);
    cudaEventCreateWithFlags(&evFeat, cudaEventDisableTiming);
    cudaEventCreateWithFlags(&evB,    cudaEventDisableTiming);

    cudaEventRecord(evFork, 0);
    cudaStreamWaitEvent(sB, evFork, 0);

    // ---- branch B (stream sB): feature convert + full MLP chain ----
    k_cvt_feat<<<(NN*64 + 255)/256, 256, 0, sB>>>((const float4*)features, F16);
    cudaEventRecord(evFeat, sB);
    k_cvt_w<<<(256*256 + 255)/256, 256, 0, sB>>>(mlp_w1, M1h, 256);
    k_cvt_w<<<(128*256 + 255)/256, 256, 0, sB>>>(mlp_w2, M2h, 128);
    {   // hidden = relu(X @ mlp_w1 + b1) -> HID fp16
        dim3 grid(2, MT);
        k_hgemm<<<grid, 256, SMEM_BYTES, sB>>>(F16, M1h, mlp_b1,
                                               nullptr, 0, HID, 256, NN, 1);
    }
    {   // self_out = hidden @ mlp_w2 + b2 -> out[:,0:128]
        dim3 grid(1, MT);
        k_hgemm<<<grid, 256, SMEM_BYTES, sB>>>(HID, M2h, mlp_b2,
                                               out, 512, nullptr, 0, NN, 0);
    }
    cudaEventRecord(evB, sB);

    // ---- branch A (legacy stream): CSR build + conv chain ----
    k_clear_cnt<<<N_BLKS, 256>>>();
    k_hist<<<E_BLKS, 256>>>(edge_dst);
    k_scan<<<1, 1024>>>();
    k_scatter<<<E_BLKS, 256>>>(edge_src, edge_dst, edge_w);
    k_cvt_w<<<(256*256 + 255)/256, 256>>>(W1, W1h, 256);
    k_cvt_w<<<(128*256 + 255)/256, 256>>>(W2, W2h, 128);

    // t1 = A @ X  needs F16 from branch B
    cudaStreamWaitEvent(0, evFeat, 0);
    k_spmm256h<<<SPMM_BLKS, 256>>>(F16, T1);

    {   // h1 = relu(t1 @ W1) -> out[:,128:384] fp32 AND H1 fp16
        dim3 grid(2, MT);
        k_hgemm<<<grid, 256, SMEM_BYTES>>>(T1, W1h, nullptr,
                                           out + 128, 512, H1, 256, NN, 1);
    }
    {   // g = h1 @ W2 -> B3h fp16
        dim3 grid(1, MT);
        k_hgemm<<<grid, 256, SMEM_BYTES>>>(H1, W2h, nullptr,
                                           nullptr, 0, B3h, 128, NN, 0);
    }
    // h2 = A @ g -> out[:,384:512]
    k_spmm128h<<<SPMM_BLKS, 256>>>(B3h, out + 384, 512);

    // ---- join ----
    cudaStreamWaitEvent(0, evB, 0);

    (void)in_sizes; (void)n_in; (void)out_size;
}